// round 1
// baseline (speedup 1.0000x reference)
#include <cuda_runtime.h>
#include <math.h>

#define NN 50000
#define NE 800000
#define HD 64
#define NC 10

// ---------------- scratch (device globals; no allocations allowed) ------------
__device__ __align__(256) float gA[NN * HD];
__device__ __align__(256) float gB[NN * HD];
__device__ __align__(256) float gC[NN * NC];
__device__ __align__(256) float gD[NN * NC];
__device__ int g_src[NE];
__device__ int g_dst[NE];
__device__ int g_is64;

// ---------------- edge index dtype detect + repack ---------------------------
__global__ void detect_k(const void* ei) {
    if (threadIdx.x == 0 && blockIdx.x == 0) {
        const long long* p = (const long long*)ei;
        int ok = 1;
        for (int i = 0; i < 1024; i++) {
            long long v = p[i];
            if (v < 0 || v >= NN) { ok = 0; break; }
        }
        g_is64 = ok;
    }
}

__global__ void prep_k(const void* ei) {
    int i = blockIdx.x * blockDim.x + threadIdx.x;
    if (i >= NE) return;
    if (g_is64) {
        const long long* p = (const long long*)ei;
        g_src[i] = (int)p[i];
        g_dst[i] = (int)p[NE + i];
    } else {
        const int* p = (const int*)ei;
        g_src[i] = p[i];
        g_dst[i] = p[NE + i];
    }
}

// ---------------- GEMM: [NN,64] @ [64,64] -------------------------------------
__global__ void __launch_bounds__(256) gemm64_k(const float* __restrict__ in,
                                                const float* __restrict__ W,
                                                float* __restrict__ out) {
    __shared__ float Ws[64 * 64];
    __shared__ float Xs[64 * 64];
    int t = threadIdx.x;
    int row0 = blockIdx.x * 64;
    for (int i = t; i < 4096; i += 256) Ws[i] = W[i];
    for (int i = t; i < 4096; i += 256) {
        int r = row0 + (i >> 6);
        Xs[i] = (r < NN) ? in[r * 64 + (i & 63)] : 0.f;
    }
    __syncthreads();
    int col = t & 63;
    int rg = t >> 6;  // 0..3
    for (int ri = rg; ri < 64; ri += 4) {
        int r = row0 + ri;
        if (r >= NN) break;
        float s = 0.f;
        #pragma unroll
        for (int k = 0; k < 64; k++) s = fmaf(Xs[ri * 64 + k], Ws[k * 64 + col], s);
        out[r * 64 + col] = s;
    }
}

// ---------------- GEMM: [NN,64] @ [64,10] -------------------------------------
__global__ void __launch_bounds__(640) gemm10_k(const float* __restrict__ in,
                                                const float* __restrict__ W,
                                                float* __restrict__ out) {
    __shared__ float Ws[64 * NC];
    __shared__ float Xs[64 * 64];
    int t = threadIdx.x;
    int row0 = blockIdx.x * 64;
    for (int i = t; i < 64 * NC; i += 640) Ws[i] = W[i];
    for (int i = t; i < 4096; i += 640) {
        int r = row0 + (i >> 6);
        Xs[i] = (r < NN) ? in[r * 64 + (i & 63)] : 0.f;
    }
    __syncthreads();
    int row = t / NC;
    int col = t - row * NC;
    int r = row0 + row;
    if (r >= NN) return;
    float s = 0.f;
    #pragma unroll
    for (int k = 0; k < 64; k++) s = fmaf(Xs[row * 64 + k], Ws[k * NC + col], s);
    out[r * NC + col] = s;
}

// ---------------- init agg rows with bias -------------------------------------
__global__ void initb_k(float* __restrict__ agg, const float* __restrict__ b,
                        int cols, int total) {
    int i = blockIdx.x * blockDim.x + threadIdx.x;
    if (i < total) {
        int c = i % cols;
        agg[i] = b[c];
    }
}

// ---------------- edge scatter: 64-channel via float4 RED.128 -----------------
__global__ void __launch_bounds__(256) scatter64_k(const float4* __restrict__ h4,
                                                   const float* __restrict__ ew,
                                                   float4* agg4) {
    int i = blockIdx.x * blockDim.x + threadIdx.x;
    if (i >= NE * 16) return;
    int e = i >> 4;
    int c = i & 15;
    int s = g_src[e];
    int d = g_dst[e];
    float w = ew[e];
    float4 v = h4[s * 16 + c];
    float4 o = make_float4(v.x * w, v.y * w, v.z * w, v.w * w);
    atomicAdd(&agg4[d * 16 + c], o);
}

// ---------------- edge scatter: 10-channel via float2 RED.64 ------------------
__global__ void __launch_bounds__(256) scatter10_k(const float2* __restrict__ h2,
                                                   const float* __restrict__ ew,
                                                   float2* agg2) {
    int i = blockIdx.x * blockDim.x + threadIdx.x;
    if (i >= NE * 5) return;
    int e = i / 5;
    int c = i - e * 5;
    int s = g_src[e];
    int d = g_dst[e];
    float w = ew[e];
    float2 v = h2[s * 5 + c];
    atomicAdd(&agg2[d * 5 + c], make_float2(v.x * w, v.y * w));
}

// ---------------- softmax over 64 channels (warp per row) ---------------------
__global__ void __launch_bounds__(256) softmax64_k(const float* __restrict__ in,
                                                   float* __restrict__ out) {
    int warp = (blockIdx.x * blockDim.x + threadIdx.x) >> 5;
    int lane = threadIdx.x & 31;
    if (warp >= NN) return;
    float v0 = in[warp * 64 + lane];
    float v1 = in[warp * 64 + 32 + lane];
    float m = fmaxf(v0, v1);
    #pragma unroll
    for (int o = 16; o; o >>= 1) m = fmaxf(m, __shfl_xor_sync(0xFFFFFFFFu, m, o));
    float e0 = __expf(v0 - m);
    float e1 = __expf(v1 - m);
    float s = e0 + e1;
    #pragma unroll
    for (int o = 16; o; o >>= 1) s += __shfl_xor_sync(0xFFFFFFFFu, s, o);
    float inv = 1.f / s;
    out[warp * 64 + lane] = e0 * inv;
    out[warp * 64 + 32 + lane] = e1 * inv;
}

// ---------------- softmax over 10 channels (thread per row) -------------------
__global__ void __launch_bounds__(256) softmax10_k(const float* __restrict__ in,
                                                   float* __restrict__ out) {
    int r = blockIdx.x * blockDim.x + threadIdx.x;
    if (r >= NN) return;
    float v[NC];
    float m = -INFINITY;
    #pragma unroll
    for (int c = 0; c < NC; c++) { v[c] = in[r * NC + c]; m = fmaxf(m, v[c]); }
    float s = 0.f;
    #pragma unroll
    for (int c = 0; c < NC; c++) { v[c] = __expf(v[c] - m); s += v[c]; }
    float inv = 1.f / s;
    #pragma unroll
    for (int c = 0; c < NC; c++) out[r * NC + c] = v[c] * inv;
}

// ---------------- launch ------------------------------------------------------
extern "C" void kernel_launch(void* const* d_in, const int* in_sizes, int n_in,
                              void* d_out, int out_size) {
    const float* x  = (const float*)d_in[0];
    const void*  ei = d_in[1];
    const float* ew = (const float*)d_in[2];
    const float* W0 = (const float*)d_in[3];
    const float* b0 = (const float*)d_in[4];
    const float* W1 = (const float*)d_in[5];
    const float* b1 = (const float*)d_in[6];
    const float* W2 = (const float*)d_in[7];
    const float* b2 = (const float*)d_in[8];
    float* out = (float*)d_out;

    float *A, *B, *C, *D;
    cudaGetSymbolAddress((void**)&A, gA);
    cudaGetSymbolAddress((void**)&B, gB);
    cudaGetSymbolAddress((void**)&C, gC);
    cudaGetSymbolAddress((void**)&D, gD);

    const int rowBlocks = (NN + 63) / 64;

    detect_k<<<1, 1>>>(ei);
    prep_k<<<(NE + 255) / 256, 256>>>(ei);

    // ---- Layer 0: h = x@W0 ; agg = scatter + b0 ; act = softmax ----
    gemm64_k<<<rowBlocks, 256>>>(x, W0, A);
    initb_k<<<(NN * HD + 255) / 256, 256>>>(B, b0, HD, NN * HD);
    scatter64_k<<<(NE * 16 + 255) / 256, 256>>>((const float4*)A, ew, (float4*)B);
    softmax64_k<<<(NN * 32 + 255) / 256, 256>>>(B, A);

    // ---- Layer 1 ----
    gemm64_k<<<rowBlocks, 256>>>(A, W1, B);
    initb_k<<<(NN * HD + 255) / 256, 256>>>(A, b1, HD, NN * HD);
    scatter64_k<<<(NE * 16 + 255) / 256, 256>>>((const float4*)B, ew, (float4*)A);
    softmax64_k<<<(NN * 32 + 255) / 256, 256>>>(A, B);

    // ---- Layer 2 (64 -> 10) ----
    gemm10_k<<<rowBlocks, 640>>>(B, W2, C);
    initb_k<<<(NN * NC + 255) / 256, 256>>>(D, b2, NC, NN * NC);
    scatter10_k<<<(NE * 5 + 255) / 256, 256>>>((const float2*)C, ew, (float2*)D);
    softmax10_k<<<(NN + 255) / 256, 256>>>(D, out);
}